// round 1
// baseline (speedup 1.0000x reference)
#include <cuda_runtime.h>
#include <cstdint>

// Problem constants
#define BDIM 2
#define SDIM 1024
#define HDIM 512
#define RDIM 64
#define TS   16           // s-rows per block
#define NBLK (BDIM * SDIM / TS)   // 128 blocks

// Padded smem strides (floats). 516%32=4 -> consecutive rows land on banks
// spaced by 4 (conflict-free for <=8 distinct rows per LDS); 516*4=2064 %16==0
// so cp.async 16B stores stay aligned. Same reasoning for 68 and 72.
#define HS_STR 516
#define HE_STR 68
#define E_STR  68
#define EP_STR 72

// Float offsets into dynamic smem
#define OFF_HS  0
#define OFF_W   (TS * HS_STR)                  // 8256
#define OFF_HE  0                              // overlays hs+W after phase 1
#define OFF_E   (OFF_W + RDIM * HS_STR)        // 41280
#define OFF_EP  (OFF_E + TS * E_STR)           // 42368
#define SMEM_FLOATS (OFF_EP + 8 * TS * EP_STR) // 51584
#define SMEM_BYTES  (SMEM_FLOATS * 4)          // 206336 bytes (< 227KB)

__device__ __forceinline__ void cpa16(float* dst, const float* src) {
    unsigned d = (unsigned)__cvta_generic_to_shared(dst);
    asm volatile("cp.async.cg.shared.global [%0], [%1], 16;\n" :: "r"(d), "l"(src));
}

__device__ __forceinline__ unsigned long long ld2(const float* p) {
    return *reinterpret_cast<const unsigned long long*>(p);
}

// Packed dual-FMA: d = a*b + d (elementwise on f32x2). ptxas will not emit
// FFMA2 from C++; this is the only way onto the full 128 FMA/cyc/SM pipe.
__device__ __forceinline__ void fma2(unsigned long long& d,
                                     unsigned long long a,
                                     unsigned long long b) {
    asm("fma.rn.f32x2 %0, %1, %2, %0;" : "+l"(d) : "l"(a), "l"(b));
}

__device__ __forceinline__ float hsum2(unsigned long long v) {
    union { unsigned long long u; float2 f; } c; c.u = v;
    return c.f.x + c.f.y;
}

__global__ __launch_bounds__(256, 1)
void cpcircuit_kernel(const float* __restrict__ hs,   // [B,S,H]
                      const float* __restrict__ Wq,   // [R,H]
                      const float* __restrict__ he,   // [H,R]
                      const float* __restrict__ cp,   // [R]
                      float* __restrict__ out)        // [B,S,H]
{
    extern __shared__ float sm[];
    float* hs_t = sm + OFF_HS;   // [TS][HS_STR]
    float* W_s  = sm + OFF_W;    // [R][HS_STR]
    float* he_s = sm + OFF_HE;   // [H][HE_STR]  (phase 2 overlay)
    float* E_s  = sm + OFF_E;    // [TS][E_STR]
    float* Ep   = sm + OFF_EP;   // [8][TS][EP_STR]

    const int t  = threadIdx.x;
    const int b  = blockIdx.x >> 6;          // 64 s-tiles per batch
    const int s0 = (blockIdx.x & 63) * TS;

    // ---- stage hs tile (16x512) and full W (64x512) into smem ----
    {
        const float* src = hs + (size_t)(b * SDIM + s0) * HDIM;
        #pragma unroll
        for (int it = 0; it < 8; ++it) {           // 2048 float4
            int idx = t + it * 256;
            int i = idx >> 7, k4 = (idx & 127) << 2;
            cpa16(hs_t + i * HS_STR + k4, src + i * HDIM + k4);
        }
        #pragma unroll
        for (int it = 0; it < 32; ++it) {          // 8192 float4
            int idx = t + it * 256;
            int r = idx >> 7, k4 = (idx & 127) << 2;
            cpa16(W_s + r * HS_STR + k4, Wq + r * HDIM + k4);
        }
        asm volatile("cp.async.commit_group;\n");
        asm volatile("cp.async.wait_group 0;\n");
        __syncthreads();
    }

    const int l  = t & 31, w = t >> 5;
    const int sb = l & 3;        // lane's s base (s = sb + 4i)
    const int rb = l >> 2;       // lane's r/h base (r = rb + 8j)

    unsigned long long acc[4][8];
    #pragma unroll
    for (int i = 0; i < 4; ++i)
        #pragma unroll
        for (int j = 0; j < 8; ++j) acc[i][j] = 0ull;

    // ---- phase 1: E_partial = hs_tile @ W^T, warp w owns k in [64w, 64w+64) ----
    {
        const int k0 = w * 64;
        #pragma unroll 4
        for (int kk = 0; kk < 32; ++kk) {
            const int k = k0 + 2 * kk;
            unsigned long long a[4], bb[8];
            #pragma unroll
            for (int i = 0; i < 4; ++i) a[i] = ld2(hs_t + (sb + 4 * i) * HS_STR + k);
            #pragma unroll
            for (int j = 0; j < 8; ++j) bb[j] = ld2(W_s + (rb + 8 * j) * HS_STR + k);
            #pragma unroll
            for (int i = 0; i < 4; ++i)
                #pragma unroll
                for (int j = 0; j < 8; ++j) fma2(acc[i][j], a[i], bb[j]);
        }
        // spill per-warp partials (conflict-free: banks 8*(s%4) + r%8 cover 0..31)
        #pragma unroll
        for (int i = 0; i < 4; ++i)
            #pragma unroll
            for (int j = 0; j < 8; ++j)
                Ep[w * (TS * EP_STR) + (sb + 4 * i) * EP_STR + (rb + 8 * j)] =
                    hsum2(acc[i][j]);
    }
    __syncthreads();

    // ---- prefetch he (512x64) into the now-dead hs+W region ----
    #pragma unroll
    for (int it = 0; it < 32; ++it) {              // 8192 float4
        int idx = t + it * 256;
        int h = idx >> 4, r4 = (idx & 15) << 2;
        cpa16(he_s + h * HE_STR + r4, he + h * RDIM + r4);
    }
    asm volatile("cp.async.commit_group;\n");

    // ---- reduce 8 k-partials -> E_s, folding cp_weight (overlaps he load) ----
    {
        int s = t >> 4, r0 = (t & 15) << 2;
        float4 v = make_float4(0.f, 0.f, 0.f, 0.f);
        #pragma unroll
        for (int ww = 0; ww < 8; ++ww) {
            const float4 p =
                *(const float4*)&Ep[ww * (TS * EP_STR) + s * EP_STR + r0];
            v.x += p.x; v.y += p.y; v.z += p.z; v.w += p.w;
        }
        v.x *= __ldg(cp + r0);     v.y *= __ldg(cp + r0 + 1);
        v.z *= __ldg(cp + r0 + 2); v.w *= __ldg(cp + r0 + 3);
        *(float4*)&E_s[s * E_STR + r0] = v;
    }
    asm volatile("cp.async.wait_group 0;\n");
    __syncthreads();

    // ---- phase 2: out = E_s @ he^T, warp w owns h in [64w, 64w+64) ----
    #pragma unroll
    for (int i = 0; i < 4; ++i)
        #pragma unroll
        for (int j = 0; j < 8; ++j) acc[i][j] = 0ull;

    {
        const int h0 = w * 64 + rb;
        #pragma unroll 4
        for (int rr = 0; rr < 32; ++rr) {
            const int r = 2 * rr;
            unsigned long long e[4], hh[8];
            #pragma unroll
            for (int i = 0; i < 4; ++i) e[i] = ld2(E_s + (sb + 4 * i) * E_STR + r);
            #pragma unroll
            for (int j = 0; j < 8; ++j) hh[j] = ld2(he_s + (h0 + 8 * j) * HE_STR + r);
            #pragma unroll
            for (int i = 0; i < 4; ++i)
                #pragma unroll
                for (int j = 0; j < 8; ++j) fma2(acc[i][j], e[i], hh[j]);
        }
    }

    // ---- store: out[b][s0+s][h], full coverage, 32B-sector coalesced ----
    {
        float* ob = out + (size_t)(b * SDIM + s0) * HDIM;
        #pragma unroll
        for (int i = 0; i < 4; ++i) {
            float* orow = ob + (sb + 4 * i) * HDIM + w * 64 + rb;
            #pragma unroll
            for (int j = 0; j < 8; ++j) orow[8 * j] = hsum2(acc[i][j]);
        }
    }
}

extern "C" void kernel_launch(void* const* d_in, const int* in_sizes, int n_in,
                              void* d_out, int out_size) {
    // metadata order: hidden_states, all_indices (unused: enumerates (s,h)
    // row-major per setup_inputs), W_seq, hidden_embeddings, cp_weight
    const float* hs = (const float*)d_in[0];
    const float* Wq = (const float*)d_in[2];
    const float* he = (const float*)d_in[3];
    const float* cp = (const float*)d_in[4];
    float* out = (float*)d_out;

    cudaFuncSetAttribute(cpcircuit_kernel,
                         cudaFuncAttributeMaxDynamicSharedMemorySize, SMEM_BYTES);
    cpcircuit_kernel<<<NBLK, 256, SMEM_BYTES>>>(hs, Wq, he, cp, out);
}

// round 2
// speedup vs baseline: 1.1742x; 1.1742x over previous
#include <cuda_runtime.h>
#include <cstdint>

// Problem constants
#define BDIM 2
#define SDIM 1024
#define HDIM 512
#define RDIM 64
#define TS   16                    // s-rows per block
#define NBLK (BDIM * SDIM / TS)    // 128 blocks

// Padded smem strides (floats). 516%32=4 -> row step hits bank+4 (conflict-free
// for the 8-distinct-row LDS patterns below); 516*4 bytes %16==0 keeps cp.async
// 16B stores aligned. Same reasoning for 68 and 72.
#define HS_STR 516
#define E_STR  68
#define EP_STR 72

// Float offsets into dynamic smem
#define OFF_HS  0
#define OFF_W   (TS * HS_STR)                   // 8256
#define OFF_E   (OFF_W + RDIM * HS_STR)         // 41280
#define OFF_EP  (OFF_E + TS * E_STR)            // 42368
#define SMEM_FLOATS (OFF_EP + 8 * TS * EP_STR)  // 51584
#define SMEM_BYTES  (SMEM_FLOATS * 4)           // 206336 bytes (< 227KB)

__device__ __forceinline__ void cpa16(float* dst, const float* src) {
    unsigned d = (unsigned)__cvta_generic_to_shared(dst);
    asm volatile("cp.async.cg.shared.global [%0], [%1], 16;\n" :: "r"(d), "l"(src));
}

__device__ __forceinline__ unsigned long long ld2(const float* p) {
    return *reinterpret_cast<const unsigned long long*>(p);
}

// Packed dual-FMA: d = a*b + d elementwise on f32x2 (128 FMA/cyc/SM pipe).
__device__ __forceinline__ void fma2(unsigned long long& d,
                                     unsigned long long a,
                                     unsigned long long b) {
    asm("fma.rn.f32x2 %0, %1, %2, %0;" : "+l"(d) : "l"(a), "l"(b));
}

__device__ __forceinline__ float hsum2(unsigned long long v) {
    union { unsigned long long u; float2 f; } c; c.u = v;
    return c.f.x + c.f.y;
}

__global__ __launch_bounds__(512, 1)
void cpcircuit_kernel(const float* __restrict__ hs,   // [B,S,H]
                      const float* __restrict__ Wq,   // [R,H]
                      const float* __restrict__ he,   // [H,R]
                      const float* __restrict__ cp,   // [R]
                      float* __restrict__ out)        // [B,S,H]
{
    extern __shared__ float sm[];
    float* hs_t = sm + OFF_HS;   // [TS][HS_STR]
    float* W_s  = sm + OFF_W;    // [R][HS_STR]; per-pair regions overlaid by he
    float* E_s  = sm + OFF_E;    // [TS][E_STR]
    float* Ep   = sm + OFF_EP;   // [8][TS][EP_STR]

    const int t    = threadIdx.x;
    const int l    = t & 31;
    const int w    = t >> 5;     // 16 warps
    const int p    = w >> 1;     // 8 warp-pairs; pair p owns k in [64p, 64p+64)
    const int half = w & 1;      // s-half within the pair
    const int b    = blockIdx.x >> 6;
    const int s0   = (blockIdx.x & 63) * TS;

    // ---- per-warp self-staging: exactly the hs/W slice this pair consumes ----
    // hs: rows [8*half, 8*half+8), cols [64p, 64p+64)   (2KB)
    // W : all 64 rows, cols [64p+32*half, +32)           (8KB, pair-split)
    {
        const float* hsrc = hs + (size_t)(b * SDIM + s0 + 8 * half) * HDIM + 64 * p;
        #pragma unroll
        for (int c = 0; c < 4; ++c) {
            int flat = l + 32 * c;
            int row = flat >> 4, kc = (flat & 15) << 2;
            cpa16(hs_t + (8 * half + row) * HS_STR + 64 * p + kc,
                  hsrc + row * HDIM + kc);
        }
        const int kbase = 64 * p + 32 * half;
        #pragma unroll
        for (int c = 0; c < 16; ++c) {
            int flat = l + 32 * c;
            int r = flat >> 3, kc = (flat & 7) << 2;
            cpa16(W_s + r * HS_STR + kbase + kc, Wq + r * HDIM + kbase + kc);
        }
        asm volatile("cp.async.commit_group;\n");
        asm volatile("cp.async.wait_group 0;\n");
        asm volatile("bar.sync %0, 64;\n" :: "r"(1 + p));  // pair barrier
    }

    const int sb = l & 3;        // lane s base
    const int rb = l >> 2;       // lane r/h base

    // ---- phase 1: E_partial(pair p, s-half) = hs @ W^T over k-slice ----
    unsigned long long acc[2][8];
    #pragma unroll
    for (int i = 0; i < 2; ++i)
        #pragma unroll
        for (int j = 0; j < 8; ++j) acc[i][j] = 0ull;
    {
        const float* ha = hs_t + (8 * half + sb) * HS_STR + 64 * p;
        const float* wb = W_s + rb * HS_STR + 64 * p;
        #pragma unroll 4
        for (int kk = 0; kk < 32; ++kk) {
            const int k = 2 * kk;
            unsigned long long a[2], bb[8];
            a[0] = ld2(ha + k);
            a[1] = ld2(ha + 4 * HS_STR + k);
            #pragma unroll
            for (int j = 0; j < 8; ++j) bb[j] = ld2(wb + (8 * j) * HS_STR + k);
            #pragma unroll
            for (int i = 0; i < 2; ++i)
                #pragma unroll
                for (int j = 0; j < 8; ++j) fma2(acc[i][j], a[i], bb[j]);
        }
        #pragma unroll
        for (int i = 0; i < 2; ++i)
            #pragma unroll
            for (int j = 0; j < 8; ++j)
                Ep[p * (TS * EP_STR) + (8 * half + sb + 4 * i) * EP_STR + rb + 8 * j]
                    = hsum2(acc[i][j]);
    }

    // ---- pair done with its W region -> immediately stream in he overlay ----
    // he row h lives at W_s[(h&63)][64*(h>>6) .. +64)  (one 256B row chunk).
    // Phase-2 warp w needs h in [32w, 32w+32) -> region of pair (w>>1) == the
    // region this pair just freed.
    asm volatile("bar.sync %0, 64;\n" :: "r"(1 + p));  // both pair warps done
    {
        #pragma unroll
        for (int c = 0; c < 16; ++c) {
            int flat = l + 32 * c;
            int hl = flat >> 4, rc = (flat & 15) << 2;
            int h = 32 * w + hl;
            cpa16(W_s + (h & 63) * HS_STR + (h >> 6) * 64 + rc,
                  he + h * RDIM + rc);
        }
        asm volatile("cp.async.commit_group;\n");
    }
    __syncthreads();

    // ---- reduce 8 k-partials -> E_s, fold cp_weight (overlaps he arrival) ----
    if (t < 256) {
        int s = t >> 4, r0 = (t & 15) << 2;
        float4 v = make_float4(0.f, 0.f, 0.f, 0.f);
        #pragma unroll
        for (int pp = 0; pp < 8; ++pp) {
            const float4 q =
                *(const float4*)&Ep[pp * (TS * EP_STR) + s * EP_STR + r0];
            v.x += q.x; v.y += q.y; v.z += q.z; v.w += q.w;
        }
        v.x *= __ldg(cp + r0);     v.y *= __ldg(cp + r0 + 1);
        v.z *= __ldg(cp + r0 + 2); v.w *= __ldg(cp + r0 + 3);
        *(float4*)&E_s[s * E_STR + r0] = v;
    }
    asm volatile("cp.async.wait_group 0;\n");
    __syncthreads();

    // ---- phase 2: out = E_s @ he^T, warp w owns h in [32w, 32w+32) ----
    unsigned long long acc2[4][4];
    #pragma unroll
    for (int i = 0; i < 4; ++i)
        #pragma unroll
        for (int j = 0; j < 4; ++j) acc2[i][j] = 0ull;
    {
        // he(h, r) at W_s + (32*half + rb + 8j)*HS_STR + p*64 + r
        const float* hb = W_s + (32 * half + rb) * HS_STR + p * 64;
        const float* eb = E_s + sb * E_STR;
        #pragma unroll 4
        for (int rr = 0; rr < 32; ++rr) {
            const int r = 2 * rr;
            unsigned long long e[4], hh[4];
            #pragma unroll
            for (int i = 0; i < 4; ++i) e[i] = ld2(eb + (4 * i) * E_STR + r);
            #pragma unroll
            for (int j = 0; j < 4; ++j) hh[j] = ld2(hb + (8 * j) * HS_STR + r);
            #pragma unroll
            for (int i = 0; i < 4; ++i)
                #pragma unroll
                for (int j = 0; j < 4; ++j) fma2(acc2[i][j], e[i], hh[j]);
        }
    }

    // ---- store out[b][s0+s][32w + rb + 8j]: 8 consecutive h per sector ----
    {
        float* ob = out + (size_t)(b * SDIM + s0) * HDIM + 32 * w + rb;
        #pragma unroll
        for (int i = 0; i < 4; ++i) {
            float* orow = ob + (sb + 4 * i) * HDIM;
            #pragma unroll
            for (int j = 0; j < 4; ++j) orow[8 * j] = hsum2(acc2[i][j]);
        }
    }
}

extern "C" void kernel_launch(void* const* d_in, const int* in_sizes, int n_in,
                              void* d_out, int out_size) {
    // metadata order: hidden_states, all_indices (unused: it enumerates (s,h)
    // row-major per setup_inputs), W_seq, hidden_embeddings, cp_weight
    const float* hs = (const float*)d_in[0];
    const float* Wq = (const float*)d_in[2];
    const float* he = (const float*)d_in[3];
    const float* cp = (const float*)d_in[4];
    float* out = (float*)d_out;

    cudaFuncSetAttribute(cpcircuit_kernel,
                         cudaFuncAttributeMaxDynamicSharedMemorySize, SMEM_BYTES);
    cpcircuit_kernel<<<NBLK, 512, SMEM_BYTES>>>(hs, Wq, he, cp, out);
}

// round 3
// speedup vs baseline: 1.3163x; 1.1210x over previous
#include <cuda_runtime.h>
#include <cstdint>

#define BDIM 2
#define SDIM 1024
#define HDIM 512
#define RDIM 64
#define TS   16
#define NBLK 128           // (2*1024/16)

// Byte offsets into dynamic smem (all regions 1024-aligned, zero padding):
//   hs : [16][512] f32, row-swizzled            32KB  @ 0
//   W  : [64][512] f32, row-swizzled           128KB  @ 32768
//   he : [512][64] f32 OVERLAYS W region exactly (dead after phase 1)
//   E  : [16][64]  f32, row-swizzled             4KB  @ 163840
//   Ep : [8][16][72] f32 partials               36.9KB @ 167936
// Swizzle: float4 column c4 of row r stored at c4 ^ (r&7)  (16B granularity).
#define OFF_HS 0
#define OFF_W  32768
#define OFF_HE 32768
#define OFF_E  163840
#define OFF_EP 167936
#define EP_STR 72
#define SMEM_BYTES (OFF_EP + 8 * TS * EP_STR * 4)   // 204800 (< 227KB)

__device__ __forceinline__ void cpa16(char* dst, const float* src) {
    unsigned d = (unsigned)__cvta_generic_to_shared(dst);
    asm volatile("cp.async.cg.shared.global [%0], [%1], 16;\n" :: "r"(d), "l"(src));
}

// Packed dual-FMA: d += a*b elementwise on f32x2.
__device__ __forceinline__ void fma2(unsigned long long& d,
                                     unsigned long long a,
                                     unsigned long long b) {
    asm("fma.rn.f32x2 %0, %1, %2, %0;" : "+l"(d) : "l"(a), "l"(b));
}

__device__ __forceinline__ float hsum2(unsigned long long v) {
    union { unsigned long long u; float2 f; } c; c.u = v;
    return c.f.x + c.f.y;
}

__global__ __launch_bounds__(512, 1)
void cpcircuit_kernel(const float* __restrict__ hs,   // [B,S,H]
                      const float* __restrict__ Wq,   // [R,H]
                      const float* __restrict__ he,   // [H,R]
                      const float* __restrict__ cp,   // [R]
                      float* __restrict__ out)        // [B,S,H]
{
    extern __shared__ char sm[];
    const int t  = threadIdx.x;
    const int l  = t & 31;
    const int w  = t >> 5;       // 16 warps
    const int kh = w >> 1;       // k-slice [64kh, 64kh+64)
    const int rh = w & 1;        // r-half (phase 1) / s-half of staging
    const int b  = blockIdx.x >> 6;
    const int s0 = (blockIdx.x & 63) * TS;

    // ---- self-staging: warp loads exactly the hs/W slices it (and its pair
    //      partner) consume. hs rows [8rh,+8) x c4 [16kh,+16); W rows [32rh,+32).
    {
        const float* hsg = hs + (size_t)(b * SDIM + s0) * HDIM;
        #pragma unroll
        for (int it = 0; it < 4; ++it) {
            int flat = l + 32 * it;               // 0..127
            int row = 8 * rh + (flat >> 4), c4 = flat & 15;
            cpa16(sm + OFF_HS + row * 2048 + kh * 256 + ((c4 ^ (row & 7)) << 4),
                  hsg + row * HDIM + kh * 64 + c4 * 4);
        }
        #pragma unroll
        for (int it = 0; it < 16; ++it) {
            int flat = l + 32 * it;               // 0..511
            int row = 32 * rh + (flat >> 4), c4 = flat & 15;
            cpa16(sm + OFF_W + row * 2048 + kh * 256 + ((c4 ^ (row & 7)) << 4),
                  Wq + row * HDIM + kh * 64 + c4 * 4);
        }
        asm volatile("cp.async.commit_group;\n");
        asm volatile("cp.async.wait_group 0;\n");
        asm volatile("bar.sync %0, 64;\n" :: "r"(1 + kh));   // pair barrier
    }

    const int sb = l & 3;        // s = sb + 4i
    const int rb = l >> 2;       // r/h = 32*x + rb + 8j

    // ---- phase 1: warp (kh,rh) computes E-partial(s 0..15, r in [32rh,+32))
    //      over its 64-wide k-slice. Per-lane tile 4s x 4r, f32x2-packed k.
    unsigned long long acc[4][4];
    #pragma unroll
    for (int i = 0; i < 4; ++i)
        #pragma unroll
        for (int j = 0; j < 4; ++j) acc[i][j] = 0ull;
    {
        int abase[4], bbase[4];
        #pragma unroll
        for (int i = 0; i < 4; ++i) {
            int s = sb + 4 * i;
            abase[i] = OFF_HS + s * 2048 + kh * 256 + ((s & 7) << 4);
        }
        #pragma unroll
        for (int j = 0; j < 4; ++j) {
            int r = 32 * rh + rb + 8 * j;          // r&7 == rb
            bbase[j] = OFF_W + r * 2048 + kh * 256 + (rb << 4);
        }
        #pragma unroll
        for (int c = 0; c < 16; ++c) {             // 4 k per step
            ulonglong2 a[4], bv[4];
            #pragma unroll
            for (int i = 0; i < 4; ++i)
                a[i] = *(const ulonglong2*)(sm + (abase[i] ^ (c << 4)));
            #pragma unroll
            for (int j = 0; j < 4; ++j)
                bv[j] = *(const ulonglong2*)(sm + (bbase[j] ^ (c << 4)));
            #pragma unroll
            for (int i = 0; i < 4; ++i)
                #pragma unroll
                for (int j = 0; j < 4; ++j) {
                    fma2(acc[i][j], a[i].x, bv[j].x);
                    fma2(acc[i][j], a[i].y, bv[j].y);
                }
        }
        // spill partials (conflict-free: bank = 8*sb + rb + const)
        float* Ep = (float*)(sm + OFF_EP);
        #pragma unroll
        for (int i = 0; i < 4; ++i)
            #pragma unroll
            for (int j = 0; j < 4; ++j)
                Ep[kh * (TS * EP_STR) + (sb + 4 * i) * EP_STR + 32 * rh + rb + 8 * j]
                    = hsum2(acc[i][j]);
    }

    // ---- pair done reading its W k-slice -> overlay that exact region with
    //      the he rows phase 2 will read there: h = 8m + kh, m in [32rh,+32).
    asm volatile("bar.sync %0, 64;\n" :: "r"(1 + kh));
    #pragma unroll
    for (int it = 0; it < 16; ++it) {
        int flat = l + 32 * it;                    // 0..511
        int m = 32 * rh + (flat >> 4), c4 = flat & 15;
        cpa16(sm + OFF_HE + m * 2048 + kh * 256 + ((c4 ^ kh) << 4),
              he + (8 * m + kh) * RDIM + c4 * 4);
    }
    asm volatile("cp.async.commit_group;\n");
    __syncthreads();                               // all Ep spills visible

    // ---- reduce 8 k-partials -> E (cp folded), overlapping he arrival ----
    if (t < 256) {
        int s = t >> 4, r4 = t & 15;
        const float* Ep = (const float*)(sm + OFF_EP);
        float4 v = make_float4(0.f, 0.f, 0.f, 0.f);
        #pragma unroll
        for (int q = 0; q < 8; ++q) {
            const float4 p = *(const float4*)(Ep + q * (TS * EP_STR) + s * EP_STR + r4 * 4);
            v.x += p.x; v.y += p.y; v.z += p.z; v.w += p.w;
        }
        v.x *= __ldg(cp + 4 * r4);     v.y *= __ldg(cp + 4 * r4 + 1);
        v.z *= __ldg(cp + 4 * r4 + 2); v.w *= __ldg(cp + 4 * r4 + 3);
        *(float4*)(sm + OFF_E + s * 256 + ((r4 ^ (s & 7)) << 4)) = v;
    }
    asm volatile("cp.async.wait_group 0;\n");
    __syncthreads();

    // ---- phase 2: warp w computes out(s 0..15, h in [32w,+32)), K=64 ----
    unsigned long long acc2[4][4];
    #pragma unroll
    for (int i = 0; i < 4; ++i)
        #pragma unroll
        for (int j = 0; j < 4; ++j) acc2[i][j] = 0ull;
    {
        const int hb = rb;                         // h = 32w + hb + 8j; h&7 == hb
        int ebase[4], hbase[4];
        #pragma unroll
        for (int i = 0; i < 4; ++i) {
            int s = sb + 4 * i;
            ebase[i] = OFF_E + s * 256 + ((s & 7) << 4);
        }
        #pragma unroll
        for (int j = 0; j < 4; ++j)
            hbase[j] = OFF_HE + (4 * w + j) * 2048 + hb * 256 + (hb << 4);
        #pragma unroll
        for (int c = 0; c < 16; ++c) {             // 4 r per step
            ulonglong2 a[4], bv[4];
            #pragma unroll
            for (int i = 0; i < 4; ++i)
                a[i] = *(const ulonglong2*)(sm + (ebase[i] ^ (c << 4)));
            #pragma unroll
            for (int j = 0; j < 4; ++j)
                bv[j] = *(const ulonglong2*)(sm + (hbase[j] ^ (c << 4)));
            #pragma unroll
            for (int i = 0; i < 4; ++i)
                #pragma unroll
                for (int j = 0; j < 4; ++j) {
                    fma2(acc2[i][j], a[i].x, bv[j].x);
                    fma2(acc2[i][j], a[i].y, bv[j].y);
                }
        }
    }

    // ---- store out[b][s0+s][32w + hb + 8j] (32B sectors, hb-contiguous) ----
    {
        float* ob = out + (size_t)(b * SDIM + s0) * HDIM + 32 * w + rb;
        #pragma unroll
        for (int i = 0; i < 4; ++i) {
            float* orow = ob + (sb + 4 * i) * HDIM;
            #pragma unroll
            for (int j = 0; j < 4; ++j) orow[8 * j] = hsum2(acc2[i][j]);
        }
    }
}

extern "C" void kernel_launch(void* const* d_in, const int* in_sizes, int n_in,
                              void* d_out, int out_size) {
    // metadata order: hidden_states, all_indices (unused: enumerates (s,h)
    // row-major per setup_inputs), W_seq, hidden_embeddings, cp_weight
    const float* hs = (const float*)d_in[0];
    const float* Wq = (const float*)d_in[2];
    const float* he = (const float*)d_in[3];
    const float* cp = (const float*)d_in[4];
    float* out = (float*)d_out;

    cudaFuncSetAttribute(cpcircuit_kernel,
                         cudaFuncAttributeMaxDynamicSharedMemorySize, SMEM_BYTES);
    cpcircuit_kernel<<<NBLK, 512, SMEM_BYTES>>>(hs, Wq, he, cp, out);
}

// round 9
// speedup vs baseline: 1.3391x; 1.0173x over previous
#include <cuda_runtime.h>
#include <cuda_bf16.h>
#include <cstdint>

#define SDIM 1024
#define HDIM 512
#define RDIM 64

// ---------------- precomputed bf16 hi/lo operands (device globals) ----------
// W' = cp*W : [64][512]; he : [512][64]; each as uint2-packed bf16x4 (f4 units)
__device__ __align__(16) uint2 g_Whi[8192], g_Wlo[8192];   // 64KB each
__device__ __align__(16) uint2 g_hehi[8192], g_helo[8192]; // 64KB each

// ---------------- smem layout (bytes) ----------------
// he panes: 512 rows x 144B (128B data + 16 pad)  -> 73728 per half
// W  bufs : 2 x (hi 64x144 + lo 64x144)           -> 18432 per buf
// hs panes: 16 rows x 1040B (1024 data + 16 pad)  -> 16640 per half
// E  panes: 16 rows x 144B                        -> 2304 per half
#define OFF_HEHI 0
#define OFF_HELO 73728
#define OFF_WBUF 147456
#define OFF_HSHI 184320
#define OFF_HSLO 200960
#define OFF_EHI  217600
#define OFF_ELO  219904
#define SMEM_BYTES 222208

static __device__ __forceinline__ uint32_t s2u(const void* p) {
    uint32_t a;
    asm("{ .reg .u64 t; cvta.to.shared.u64 t, %1; cvt.u32.u64 %0, t; }"
        : "=r"(a) : "l"(p));
    return a;
}
static __device__ __forceinline__ void cpa16(uint32_t dst, const void* src) {
    asm volatile("cp.async.cg.shared.global [%0], [%1], 16;\n"
                 :: "r"(dst), "l"(src));
}
// pack (v0 -> low half, v1 -> high half)
static __device__ __forceinline__ uint32_t pk(float v0, float v1) {
    uint32_t d;
    asm("cvt.rn.bf16x2.f32 %0, %1, %2;" : "=r"(d) : "f"(v1), "f"(v0));
    return d;
}
static __device__ __forceinline__ float bt(float x, float& rem) {
    float xh = __bfloat162float(__float2bfloat16_rn(x));
    rem = x - xh;
    return xh;
}
static __device__ __forceinline__ void split4(float4 v, uint2& h, uint2& lo) {
    float l0, l1, l2, l3;
    float h0 = bt(v.x, l0), h1 = bt(v.y, l1), h2 = bt(v.z, l2), h3 = bt(v.w, l3);
    h.x  = pk(h0, h1); h.y  = pk(h2, h3);
    lo.x = pk(l0, l1); lo.y = pk(l2, l3);
}

#define LDSM4(r, a) \
    asm volatile("ldmatrix.sync.aligned.m8n8.x4.shared.b16 {%0,%1,%2,%3}, [%4];" \
        : "=r"((r)[0]), "=r"((r)[1]), "=r"((r)[2]), "=r"((r)[3]) : "r"(a))
// B operand: NON-trans. mma.m16n8k16.row.col B fragment is lane j ->
// (k = 2*(j&3)+{0,1}, n = j>>2): consecutive-k pairs, which is exactly what a
// plain m8n8 load of n-major/k-contiguous storage produces. (.trans was the
// round-8 bug: it swaps k<->n inside each 8x8 tile.)
#define LDSM2(r, a) \
    asm volatile("ldmatrix.sync.aligned.m8n8.x2.shared.b16 {%0,%1}, [%2];" \
        : "=r"((r)[0]), "=r"((r)[1]) : "r"(a))

static __device__ __forceinline__ void mma16816(float c[4], const uint32_t a[4],
                                                const uint32_t b[2]) {
    asm volatile("mma.sync.aligned.m16n8k16.row.col.f32.bf16.bf16.f32 "
                 "{%0,%1,%2,%3}, {%4,%5,%6,%7}, {%8,%9}, {%0,%1,%2,%3};"
                 : "+f"(c[0]), "+f"(c[1]), "+f"(c[2]), "+f"(c[3])
                 : "r"(a[0]), "r"(a[1]), "r"(a[2]), "r"(a[3]),
                   "r"(b[0]), "r"(b[1]));
}

// ---------------- prep: split cp*W and he into bf16 hi/lo ----------------
__global__ void prep_kernel(const float* __restrict__ Wq,
                            const float* __restrict__ he,
                            const float* __restrict__ cp) {
    int i = blockIdx.x * 256 + threadIdx.x;          // 0..8191 float4s
    float4 v = *(const float4*)(Wq + 4 * i);
    float s = __ldg(cp + (i >> 7));                  // 128 f4 per W row
    v.x *= s; v.y *= s; v.z *= s; v.w *= s;
    uint2 h, lo;
    split4(v, h, lo);
    g_Whi[i] = h; g_Wlo[i] = lo;
    float4 u = *(const float4*)(he + 4 * i);
    split4(u, h, lo);
    g_hehi[i] = h; g_helo[i] = lo;
}

// ---------------- main: 128 blocks x 256 threads, 16 s-rows each ----------
__global__ __launch_bounds__(256, 1)
void cpc_mma(const float* __restrict__ hs, float* __restrict__ out) {
    extern __shared__ char sm[];
    const uint32_t smb = s2u(sm);
    const int t = threadIdx.x, l = t & 31, w = t >> 5;
    const int bb = blockIdx.x >> 6, s0 = (blockIdx.x & 63) * 16;

    // -- cp.async issue helpers (8 ops/thread each: 1024 x 16B) --
    auto issueW = [&](int c, int buf) {
        #pragma unroll
        for (int q = 0; q < 4; ++q) {
            int o = t + 256 * q;                       // 0..1023
            int half = o >> 9, rr = (o >> 3) & 63, seg = o & 7;
            const char* src = (const char*)(half ? g_Wlo : g_Whi)
                              + rr * 1024 + c * 128 + seg * 16;
            cpa16(smb + OFF_WBUF + buf * 18432 + half * 9216 + rr * 144 + seg * 16,
                  src);
        }
    };
    auto issueHE = [&](int sl) {
        #pragma unroll
        for (int q = 0; q < 4; ++q) {
            int o = t + 256 * q;
            int half = o >> 9, rr = (o >> 3) & 63, seg = o & 7;
            int row = sl * 64 + rr;
            const char* src = (const char*)(half ? g_helo : g_hehi)
                              + row * 128 + seg * 16;
            cpa16(smb + OFF_HEHI + half * 73728 + row * 144 + seg * 16, src);
        }
    };

    // prologue: groups G0={W0,heS0}, G1={W1,heS1}
    issueW(0, 0); issueHE(0);
    asm volatile("cp.async.commit_group;\n");
    issueW(1, 1); issueHE(1);
    asm volatile("cp.async.commit_group;\n");

    // hs tile 16x512 f32 -> split into smem panes (overlaps cp.async)
    {
        const float* g = hs + (size_t)(bb * SDIM + s0) * HDIM;
        #pragma unroll
        for (int q = 0; q < 8; ++q) {
            int i = t + 256 * q;                       // f4 idx, 0..2047
            int row = i >> 7, c4 = i & 127;
            float4 v = *(const float4*)(g + row * HDIM + c4 * 4);
            uint2 h, lo;
            split4(v, h, lo);
            *(uint2*)(sm + OFF_HSHI + row * 1040 + c4 * 8) = h;
            *(uint2*)(sm + OFF_HSLO + row * 1040 + c4 * 8) = lo;
        }
    }

    // per-lane fragment address components
    const int arow = (l & 7) + ((l >> 3) & 1) * 8;     // A row (x4 ldmatrix)
    const int akb  = (l >> 4) * 16;                    // A k-half byte off
    const int lb   = l & 15;
    const int brow = lb & 7;                           // B n-row
    const int bkb  = ((lb >> 3) & 1) * 16;             // B k-half byte off

    const uint32_t aAhi = smb + OFF_HSHI + arow * 1040 + akb;
    const uint32_t aAlo = smb + OFF_HSLO + arow * 1040 + akb;
    const uint32_t bW   = (uint32_t)((8 * w + brow) * 144 + bkb);

    // -- phase 1: E[16s][8r per warp] over K=512, 3 split passes --
    float C0[4] = {0, 0, 0, 0}, C1[4] = {0, 0, 0, 0}, C2[4] = {0, 0, 0, 0};
    #pragma unroll 1
    for (int c = 0; c < 8; ++c) {
        if (c < 7) { asm volatile("cp.async.wait_group 1;\n" ::: "memory"); }
        else       { asm volatile("cp.async.wait_group 0;\n" ::: "memory"); }
        __syncthreads();
        const uint32_t wb = smb + OFF_WBUF + (c & 1) * 18432 + bW;
        #pragma unroll
        for (int ks = 0; ks < 4; ++ks) {
            uint32_t ah[4], al[4], bh[2], bl[2];
            LDSM4(ah, aAhi + 128 * c + 32 * ks);
            LDSM4(al, aAlo + 128 * c + 32 * ks);
            LDSM2(bh, wb + 32 * ks);
            LDSM2(bl, wb + 9216 + 32 * ks);
            mma16816(C0, ah, bh);
            mma16816(C1, ah, bl);
            mma16816(C2, al, bh);
        }
        __syncthreads();
        if (c + 2 <= 7) {
            issueW(c + 2, c & 1);
            issueHE(c + 2);
            asm volatile("cp.async.commit_group;\n");
        }
    }

    // -- E split -> smem panes --
    {
        const int r1 = l >> 2, cb = 8 * w + 2 * (l & 3);
        float e0 = C0[0] + C1[0] + C2[0], e1 = C0[1] + C1[1] + C2[1];
        float e2 = C0[2] + C1[2] + C2[2], e3 = C0[3] + C1[3] + C2[3];
        float q0, q1, q2, q3;
        float h0 = bt(e0, q0), h1 = bt(e1, q1), h2 = bt(e2, q2), h3 = bt(e3, q3);
        *(uint32_t*)(sm + OFF_EHI + r1 * 144 + cb * 2)       = pk(h0, h1);
        *(uint32_t*)(sm + OFF_ELO + r1 * 144 + cb * 2)       = pk(q0, q1);
        *(uint32_t*)(sm + OFF_EHI + (r1 + 8) * 144 + cb * 2) = pk(h2, h3);
        *(uint32_t*)(sm + OFF_ELO + (r1 + 8) * 144 + cb * 2) = pk(q2, q3);
    }
    __syncthreads();

    // -- phase 2: out[16s][64h per warp] = E @ he^T, K=64, 3 passes --
    uint32_t eh[4][4], el[4][4];
    #pragma unroll
    for (int ks = 0; ks < 4; ++ks) {
        LDSM4(eh[ks], smb + OFF_EHI + arow * 144 + akb + 32 * ks);
        LDSM4(el[ks], smb + OFF_ELO + arow * 144 + akb + 32 * ks);
    }
    float C[8][4];
    #pragma unroll
    for (int j = 0; j < 8; ++j)
        #pragma unroll
        for (int k = 0; k < 4; ++k) C[j][k] = 0.f;
    uint32_t bHe[8];
    #pragma unroll
    for (int j = 0; j < 8; ++j)
        bHe[j] = smb + OFF_HEHI + (uint32_t)((64 * w + 8 * j + brow) * 144 + bkb);
    #pragma unroll
    for (int ks = 0; ks < 4; ++ks) {
        #pragma unroll
        for (int j = 0; j < 8; ++j) {
            uint32_t bh[2], bl[2];
            LDSM2(bh, bHe[j] + 32 * ks);
            LDSM2(bl, bHe[j] + 73728 + 32 * ks);
            mma16816(C[j], eh[ks], bh);
            mma16816(C[j], eh[ks], bl);
            mma16816(C[j], el[ks], bh);
        }
    }

    // -- store: rows (l>>2, +8), cols 64w + 8j + 2(l&3) + {0,1} --
    {
        const int r1 = l >> 2;
        float* o1 = out + (size_t)(bb * SDIM + s0 + r1) * HDIM + 64 * w + 2 * (l & 3);
        float* o2 = o1 + 8 * HDIM;
        #pragma unroll
        for (int j = 0; j < 8; ++j) {
            *(float2*)(o1 + 8 * j) = make_float2(C[j][0], C[j][1]);
            *(float2*)(o2 + 8 * j) = make_float2(C[j][2], C[j][3]);
        }
    }
}

extern "C" void kernel_launch(void* const* d_in, const int* in_sizes, int n_in,
                              void* d_out, int out_size) {
    // metadata order: hidden_states, all_indices (unused: enumerates (s,h)
    // row-major per setup_inputs), W_seq, hidden_embeddings, cp_weight
    const float* hs = (const float*)d_in[0];
    const float* Wq = (const float*)d_in[2];
    const float* he = (const float*)d_in[3];
    const float* cp = (const float*)d_in[4];
    float* out = (float*)d_out;

    prep_kernel<<<32, 256>>>(Wq, he, cp);
    cudaFuncSetAttribute(cpc_mma, cudaFuncAttributeMaxDynamicSharedMemorySize,
                         SMEM_BYTES);
    cpc_mma<<<128, 256, SMEM_BYTES>>>(hs, out);
}

// round 11
// speedup vs baseline: 1.3747x; 1.0266x over previous
#include <cuda_runtime.h>
#include <cuda_bf16.h>
#include <cstdint>

#define SDIM 1024
#define HDIM 512
#define RDIM 64

// ---------------- precomputed bf16 hi/lo operands (device globals) ----------
// W' = cp*W : [64][512]; he : [512][64]; each as uint2-packed bf16x4 (f4 units)
__device__ __align__(16) uint2 g_Whi[8192], g_Wlo[8192];   // 64KB each
__device__ __align__(16) uint2 g_hehi[8192], g_helo[8192]; // 64KB each

// ---------------- smem layout (bytes) ----------------
// he panes: 512 rows x 144B (128B data + 16 pad)  -> 73728 per half
// W  bufs : 2 x (hi 64x144 + lo 64x144)           -> 18432 per buf
// hs panes: 16 rows x 1040B (1024 data + 16 pad)  -> 16640 per half
// E  panes: 16 rows x 144B                        -> 2304 per half
#define OFF_HEHI 0
#define OFF_HELO 73728
#define OFF_WBUF 147456
#define OFF_HSHI 184320
#define OFF_HSLO 200960
#define OFF_EHI  217600
#define OFF_ELO  219904
#define SMEM_BYTES 222208

static __device__ __forceinline__ uint32_t s2u(const void* p) {
    uint32_t a;
    asm("{ .reg .u64 t; cvta.to.shared.u64 t, %1; cvt.u32.u64 %0, t; }"
        : "=r"(a) : "l"(p));
    return a;
}
static __device__ __forceinline__ void cpa16(uint32_t dst, const void* src) {
    asm volatile("cp.async.cg.shared.global [%0], [%1], 16;\n"
                 :: "r"(dst), "l"(src));
}
// pack (v0 -> low half, v1 -> high half)
static __device__ __forceinline__ uint32_t pk(float v0, float v1) {
    uint32_t d;
    asm("cvt.rn.bf16x2.f32 %0, %1, %2;" : "=r"(d) : "f"(v1), "f"(v0));
    return d;
}
static __device__ __forceinline__ float bt(float x, float& rem) {
    float xh = __bfloat162float(__float2bfloat16_rn(x));
    rem = x - xh;
    return xh;
}
static __device__ __forceinline__ void split4(float4 v, uint2& h, uint2& lo) {
    float l0, l1, l2, l3;
    float h0 = bt(v.x, l0), h1 = bt(v.y, l1), h2 = bt(v.z, l2), h3 = bt(v.w, l3);
    h.x  = pk(h0, h1); h.y  = pk(h2, h3);
    lo.x = pk(l0, l1); lo.y = pk(l2, l3);
}

#define LDSM4(r, a) \
    asm volatile("ldmatrix.sync.aligned.m8n8.x4.shared.b16 {%0,%1,%2,%3}, [%4];" \
        : "=r"((r)[0]), "=r"((r)[1]), "=r"((r)[2]), "=r"((r)[3]) : "r"(a))
// B operand: NON-trans (m16n8k16.row.col B fragment = consecutive-k pairs per n)
#define LDSM2(r, a) \
    asm volatile("ldmatrix.sync.aligned.m8n8.x2.shared.b16 {%0,%1}, [%2];" \
        : "=r"((r)[0]), "=r"((r)[1]) : "r"(a))

static __device__ __forceinline__ void mma16816(float c[4], const uint32_t a[4],
                                                const uint32_t b[2]) {
    asm volatile("mma.sync.aligned.m16n8k16.row.col.f32.bf16.bf16.f32 "
                 "{%0,%1,%2,%3}, {%4,%5,%6,%7}, {%8,%9}, {%0,%1,%2,%3};"
                 : "+f"(c[0]), "+f"(c[1]), "+f"(c[2]), "+f"(c[3])
                 : "r"(a[0]), "r"(a[1]), "r"(a[2]), "r"(a[3]),
                   "r"(b[0]), "r"(b[1]));
}

#define CPWAIT(n) asm volatile("cp.async.wait_group " #n ";\n" ::: "memory")

// ---------------- prep: split cp*W and he into bf16 hi/lo ----------------
__global__ void prep_kernel(const float* __restrict__ Wq,
                            const float* __restrict__ he,
                            const float* __restrict__ cp) {
    int i = blockIdx.x * 256 + threadIdx.x;          // 0..8191 float4s
    float4 v = *(const float4*)(Wq + 4 * i);
    float s = __ldg(cp + (i >> 7));                  // 128 f4 per W row
    v.x *= s; v.y *= s; v.z *= s; v.w *= s;
    uint2 h, lo;
    split4(v, h, lo);
    g_Whi[i] = h; g_Wlo[i] = lo;
    float4 u = *(const float4*)(he + 4 * i);
    split4(u, h, lo);
    g_hehi[i] = h; g_helo[i] = lo;
}

// ---------------- main: 128 blocks x 256 threads, 16 s-rows each ----------
// All streamed operands are warp-private: phase-1 warp w consumes W rows
// [8w,8w+8); phase-2 warp w consumes he rows [64w,64w+64). Each warp runs its
// own cp.async FIFO (one commit group per chunk = W chunk c + he slice c) and
// syncs with wait_group+syncwarp only. Exactly 2 block-wide barriers total.
__global__ __launch_bounds__(256, 1)
void cpc_mma(const float* __restrict__ hs, float* __restrict__ out) {
    extern __shared__ char sm[];
    const uint32_t smb = s2u(sm);
    const int t = threadIdx.x, l = t & 31, w = t >> 5;
    const int bb = blockIdx.x >> 6, s0 = (blockIdx.x & 63) * 16;

    // -- per-warp cp.async issue helpers (4 x 16B per lane per call) --
    auto issueW = [&](int c, int buf) {
        #pragma unroll
        for (int q = 0; q < 4; ++q) {
            int flat = l + 32 * q;                 // 0..127
            int pane = flat >> 6, rr = (flat >> 3) & 7, seg = flat & 7;
            int row = 8 * w + rr;
            const char* src = (const char*)(pane ? g_Wlo : g_Whi)
                              + row * 1024 + c * 128 + seg * 16;
            cpa16(smb + OFF_WBUF + buf * 18432 + pane * 9216 + row * 144 + seg * 16,
                  src);
        }
    };
    auto issueHE = [&](int s) {
        #pragma unroll
        for (int q = 0; q < 4; ++q) {
            int flat = l + 32 * q;
            int pane = flat >> 6, rr = (flat >> 3) & 7, seg = flat & 7;
            int row = 64 * w + 8 * s + rr;
            const char* src = (const char*)(pane ? g_helo : g_hehi)
                              + row * 128 + seg * 16;
            cpa16(smb + (pane ? OFF_HELO : OFF_HEHI) + row * 144 + seg * 16, src);
        }
    };

    // prologue: g0={W0}; g1={W1, he0, he1}
    issueW(0, 0);
    asm volatile("cp.async.commit_group;\n");
    issueW(1, 1); issueHE(0); issueHE(1);
    asm volatile("cp.async.commit_group;\n");

    // hs tile 16x512 f32 -> split into smem panes (overlaps cp.async)
    {
        const float* g = hs + (size_t)(bb * SDIM + s0) * HDIM;
        #pragma unroll
        for (int q = 0; q < 8; ++q) {
            int i = t + 256 * q;                   // f4 idx, 0..2047
            int row = i >> 7, c4 = i & 127;
            float4 v = *(const float4*)(g + row * HDIM + c4 * 4);
            uint2 h, lo;
            split4(v, h, lo);
            *(uint2*)(sm + OFF_HSHI + row * 1040 + c4 * 8) = h;
            *(uint2*)(sm + OFF_HSLO + row * 1040 + c4 * 8) = lo;
        }
    }
    __syncthreads();                               // barrier #1: hs panes ready

    // per-lane fragment address components
    const int arow = (l & 7) + ((l >> 3) & 1) * 8; // A row (x4 ldmatrix)
    const int akb  = (l >> 4) * 16;                // A k-half byte off
    const int lb   = l & 15;
    const int brow = lb & 7;                       // B n-row
    const int bkb  = ((lb >> 3) & 1) * 16;         // B k-half byte off

    const uint32_t aAhi = smb + OFF_HSHI + arow * 1040 + akb;
    const uint32_t aAlo = smb + OFF_HSLO + arow * 1040 + akb;
    const uint32_t bW   = (uint32_t)((8 * w + brow) * 144 + bkb);

    // -- phase 1: E[16s][8r per warp] over K=512; per-warp pipeline, no bar --
    float C0[4] = {0, 0, 0, 0}, C1[4] = {0, 0, 0, 0}, C2[4] = {0, 0, 0, 0};
    #pragma unroll 1
    for (int c = 0; c < 8; ++c) {
        // group g_c carries W chunk c; issued groups ahead: exactly one (g_{c+1})
        if (c < 7) CPWAIT(1); else CPWAIT(0);
        __syncwarp();
        const uint32_t wb = smb + OFF_WBUF + (c & 1) * 18432 + bW;
        #pragma unroll
        for (int ks = 0; ks < 4; ++ks) {
            uint32_t ah[4], al[4], bh[2], bl[2];
            LDSM4(ah, aAhi + 128 * c + 32 * ks);
            LDSM4(al, aAlo + 128 * c + 32 * ks);
            LDSM2(bh, wb + 32 * ks);
            LDSM2(bl, wb + 9216 + 32 * ks);
            mma16816(C0, ah, bh);
            mma16816(C1, ah, bl);
            mma16816(C2, al, bh);
        }
        if (c + 2 <= 7) {                          // g_{c+2} = {W chunk c+2, he slice c+2}
            issueW(c + 2, c & 1);
            issueHE(c + 2);
            asm volatile("cp.async.commit_group;\n");
        }
    }

    // -- E split -> smem panes --
    {
        const int r1 = l >> 2, cb = 8 * w + 2 * (l & 3);
        float e0 = C0[0] + C1[0] + C2[0], e1 = C0[1] + C1[1] + C2[1];
        float e2 = C0[2] + C1[2] + C2[2], e3 = C0[3] + C1[3] + C2[3];
        float q0, q1, q2, q3;
        float h0 = bt(e0, q0), h1 = bt(e1, q1), h2 = bt(e2, q2), h3 = bt(e3, q3);
        *(uint32_t*)(sm + OFF_EHI + r1 * 144 + cb * 2)       = pk(h0, h1);
        *(uint32_t*)(sm + OFF_ELO + r1 * 144 + cb * 2)       = pk(q0, q1);
        *(uint32_t*)(sm + OFF_EHI + (r1 + 8) * 144 + cb * 2) = pk(h2, h3);
        *(uint32_t*)(sm + OFF_ELO + (r1 + 8) * 144 + cb * 2) = pk(q2, q3);
    }
    __syncthreads();                               // barrier #2: E exchange

    // -- phase 2: out[16s][64h per warp] = E @ he^T, K=64, 3 passes --
    // (this warp's he rows arrived via its own groups, all drained at c=7)
    uint32_t eh[4][4], el[4][4];
    #pragma unroll
    for (int ks = 0; ks < 4; ++ks) {
        LDSM4(eh[ks], smb + OFF_EHI + arow * 144 + akb + 32 * ks);
        LDSM4(el[ks], smb + OFF_ELO + arow * 144 + akb + 32 * ks);
    }
    float C[8][4];
    #pragma unroll
    for (int j = 0; j < 8; ++j)
        #pragma unroll
        for (int k = 0; k < 4; ++k) C[j][k] = 0.f;
    uint32_t bHe[8];
    #pragma unroll
    for (int j = 0; j < 8; ++j)
        bHe[j] = smb + OFF_HEHI + (uint32_t)((64 * w + 8 * j + brow) * 144 + bkb);
    #pragma unroll
    for (int ks = 0; ks < 4; ++ks) {
        #pragma unroll
        for (int j = 0; j < 8; ++j) {
            uint32_t bh[2], bl[2];
            LDSM2(bh, bHe[j] + 32 * ks);
            LDSM2(bl, bHe[j] + 73728 + 32 * ks);
            mma16816(C[j], eh[ks], bh);
            mma16816(C[j], eh[ks], bl);
            mma16816(C[j], el[ks], bh);
        }
    }

    // -- store: rows (l>>2, +8), cols 64w + 8j + 2(l&3) + {0,1} --
    {
        const int r1 = l >> 2;
        float* o1 = out + (size_t)(bb * SDIM + s0 + r1) * HDIM + 64 * w + 2 * (l & 3);
        float* o2 = o1 + 8 * HDIM;
        #pragma unroll
        for (int j = 0; j < 8; ++j) {
            *(float2*)(o1 + 8 * j) = make_float2(C[j][0], C[j][1]);
            *(float2*)(o2 + 8 * j) = make_float2(C[j][2], C[j][3]);
        }
    }
}

extern "C" void kernel_launch(void* const* d_in, const int* in_sizes, int n_in,
                              void* d_out, int out_size) {
    // metadata order: hidden_states, all_indices (unused: enumerates (s,h)
    // row-major per setup_inputs), W_seq, hidden_embeddings, cp_weight
    const float* hs = (const float*)d_in[0];
    const float* Wq = (const float*)d_in[2];
    const float* he = (const float*)d_in[3];
    const float* cp = (const float*)d_in[4];
    float* out = (float*)d_out;

    prep_kernel<<<32, 256>>>(Wq, he, cp);
    cudaFuncSetAttribute(cpc_mma, cudaFuncAttributeMaxDynamicSharedMemorySize,
                         SMEM_BYTES);
    cpc_mma<<<128, 256, SMEM_BYTES>>>(hs, out);
}

// round 12
// speedup vs baseline: 1.5461x; 1.1247x over previous
#include <cuda_runtime.h>
#include <cuda_bf16.h>
#include <cstdint>

#define SDIM 1024
#define HDIM 512
#define RDIM 64

// ---------------- precomputed bf16 hi/lo operands (device globals) ----------
// W' = cp*W : [64][512]; he : [512][64]; each as uint2-packed bf16x4 (f4 units)
__device__ __align__(16) uint2 g_Whi[8192], g_Wlo[8192];   // 64KB each
__device__ __align__(16) uint2 g_hehi[8192], g_helo[8192]; // 64KB each

// ---------------- smem layout (bytes) ----------------
// hs panes : 16 rows x 1040B (1024 data + 16 pad), hi+lo        33280
// W bufs   : 16 warps x 2 bufs x 2 panes x 8 rows x 144B        73728
// he bufs  : same shape as W bufs                               73728
// Ep       : 2 kh x 16 rows x 272B f32 partials                  8704
// E panes  : 16 rows x 144B, hi+lo                               4608
#define OFF_HSHI 0
#define OFF_HSLO 16640
#define OFF_WB   33280
#define OFF_HEB  107008
#define OFF_EP   180736
#define OFF_EHI  189440
#define OFF_ELO  191744
#define SMEM_BYTES 194048

static __device__ __forceinline__ uint32_t s2u(const void* p) {
    uint32_t a;
    asm("{ .reg .u64 t; cvta.to.shared.u64 t, %1; cvt.u32.u64 %0, t; }"
        : "=r"(a) : "l"(p));
    return a;
}
static __device__ __forceinline__ void cpa16(uint32_t dst, const void* src) {
    asm volatile("cp.async.cg.shared.global [%0], [%1], 16;\n"
                 :: "r"(dst), "l"(src));
}
static __device__ __forceinline__ uint32_t pk(float v0, float v1) {
    uint32_t d;
    asm("cvt.rn.bf16x2.f32 %0, %1, %2;" : "=r"(d) : "f"(v1), "f"(v0));
    return d;
}
static __device__ __forceinline__ float bt(float x, float& rem) {
    float xh = __bfloat162float(__float2bfloat16_rn(x));
    rem = x - xh;
    return xh;
}
static __device__ __forceinline__ void split4(float4 v, uint2& h, uint2& lo) {
    float l0, l1, l2, l3;
    float h0 = bt(v.x, l0), h1 = bt(v.y, l1), h2 = bt(v.z, l2), h3 = bt(v.w, l3);
    h.x  = pk(h0, h1); h.y  = pk(h2, h3);
    lo.x = pk(l0, l1); lo.y = pk(l2, l3);
}

#define LDSM4(r, a) \
    asm volatile("ldmatrix.sync.aligned.m8n8.x4.shared.b16 {%0,%1,%2,%3}, [%4];" \
        : "=r"((r)[0]), "=r"((r)[1]), "=r"((r)[2]), "=r"((r)[3]) : "r"(a))
// B operand: NON-trans (m16n8k16.row.col B fragment = consecutive-k pairs per n)
#define LDSM2(r, a) \
    asm volatile("ldmatrix.sync.aligned.m8n8.x2.shared.b16 {%0,%1}, [%2];" \
        : "=r"((r)[0]), "=r"((r)[1]) : "r"(a))

static __device__ __forceinline__ void mma16816(float c[4], const uint32_t a[4],
                                                const uint32_t b[2]) {
    asm volatile("mma.sync.aligned.m16n8k16.row.col.f32.bf16.bf16.f32 "
                 "{%0,%1,%2,%3}, {%4,%5,%6,%7}, {%8,%9}, {%0,%1,%2,%3};"
                 : "+f"(c[0]), "+f"(c[1]), "+f"(c[2]), "+f"(c[3])
                 : "r"(a[0]), "r"(a[1]), "r"(a[2]), "r"(a[3]),
                   "r"(b[0]), "r"(b[1]));
}

#define CPWAIT(n) asm volatile("cp.async.wait_group " #n ";\n" ::: "memory")
#define CPCOMMIT() asm volatile("cp.async.commit_group;\n")

// ---------------- prep: split cp*W and he into bf16 hi/lo ----------------
__global__ void prep_kernel(const float* __restrict__ Wq,
                            const float* __restrict__ he,
                            const float* __restrict__ cp) {
    int i = blockIdx.x * 256 + threadIdx.x;          // 0..8191 float4s
    float4 v = *(const float4*)(Wq + 4 * i);
    float s = __ldg(cp + (i >> 7));                  // 128 f4 per W row
    v.x *= s; v.y *= s; v.z *= s; v.w *= s;
    uint2 h, lo;
    split4(v, h, lo);
    g_Whi[i] = h; g_Wlo[i] = lo;
    float4 u = *(const float4*)(he + 4 * i);
    split4(u, h, lo);
    g_hehi[i] = h; g_helo[i] = lo;
}

// ---------------- main: 128 blocks x 512 threads, 16 s-rows each ----------
// Phase 1: warp (ro=w&7, kh=w>>3) computes E-partial[16s][8r] over K=256
//          (4 chunks, warp-private W FIFO). kh-halves reduced via f32 smem.
// Phase 2: warp w owns h in [32w,32w+32), streamed as 4 sub-slices of 8 h
//          through a 2-deep warp-private he buffer.
__global__ __launch_bounds__(512, 1)
void cpc_mma(const float* __restrict__ hs, float* __restrict__ out) {
    extern __shared__ char sm[];
    const uint32_t smb = s2u(sm);
    const int t = threadIdx.x, l = t & 31, w = t >> 5;
    const int ro = w & 7, kh = w >> 3;
    const int bb = blockIdx.x >> 6, s0 = (blockIdx.x & 63) * 16;

    const uint32_t wbB  = smb + OFF_WB  + w * 4608;   // this warp's W bufs
    const uint32_t heB  = smb + OFF_HEB + w * 4608;   // this warp's he bufs

    // -- per-warp cp.async issue: 8 rows x 128B x 2 panes = 4 x 16B per lane --
    auto issueW = [&](int c, int buf) {               // c: local chunk 0..3
        int cc = 4 * kh + c;                          // global chunk
        #pragma unroll
        for (int q = 0; q < 4; ++q) {
            int flat = l + 32 * q;                    // 0..127
            int pane = flat >> 6, row = (flat >> 3) & 7, seg = flat & 7;
            const char* src = (const char*)(pane ? g_Wlo : g_Whi)
                              + (8 * ro + row) * 1024 + cc * 128 + seg * 16;
            cpa16(wbB + buf * 2304 + pane * 1152 + row * 144 + seg * 16, src);
        }
    };
    auto issueHE = [&](int ss, int buf) {             // ss: sub-slice 0..3
        #pragma unroll
        for (int q = 0; q < 4; ++q) {
            int flat = l + 32 * q;
            int pane = flat >> 6, row = (flat >> 3) & 7, seg = flat & 7;
            const char* src = (const char*)(pane ? g_helo : g_hehi)
                              + (32 * w + 8 * ss + row) * 128 + seg * 16;
            cpa16(heB + buf * 2304 + pane * 1152 + row * 144 + seg * 16, src);
        }
    };

    // prologue FIFO: G0={W0}, G1={W1, he0}
    issueW(0, 0); CPCOMMIT();
    issueW(1, 1); issueHE(0, 0); CPCOMMIT();

    // hs tile 16x512 f32 -> split panes (overlaps cp.async), 4 f4/thread
    {
        const float* g = hs + (size_t)(bb * SDIM + s0) * HDIM;
        #pragma unroll
        for (int q = 0; q < 4; ++q) {
            int i = t + 512 * q;                      // 0..2047
            int row = i >> 7, c4 = i & 127;
            float4 v = *(const float4*)(g + row * HDIM + c4 * 4);
            uint2 h, lo;
            split4(v, h, lo);
            *(uint2*)(sm + OFF_HSHI + row * 1040 + c4 * 8) = h;
            *(uint2*)(sm + OFF_HSLO + row * 1040 + c4 * 8) = lo;
        }
    }
    __syncthreads();                                  // barrier #1: hs ready

    // per-lane fragment address components
    const int arow = (l & 7) + ((l >> 3) & 1) * 8;    // A row (x4 ldmatrix)
    const int akb  = (l >> 4) * 16;                   // A k-half byte off
    const int lb   = l & 15;
    const int brow = lb & 7;                          // B n-row (local)
    const int bkb  = ((lb >> 3) & 1) * 16;            // B k16-half byte off

    const uint32_t aAhi = smb + OFF_HSHI + arow * 1040 + akb;
    const uint32_t aAlo = smb + OFF_HSLO + arow * 1040 + akb;
    const uint32_t bWl  = (uint32_t)(brow * 144 + bkb);

    // -- phase 1: 4 chunks, per-warp pipeline --
    float C0[4] = {0, 0, 0, 0}, C1[4] = {0, 0, 0, 0}, C2[4] = {0, 0, 0, 0};
    #pragma unroll 1
    for (int c = 0; c < 4; ++c) {
        if (c < 3) CPWAIT(1); else CPWAIT(0);
        __syncwarp();
        const uint32_t wb = wbB + (c & 1) * 2304 + bWl;
        const int cc = 4 * kh + c;
        #pragma unroll
        for (int ks = 0; ks < 4; ++ks) {
            uint32_t ah[4], al[4], bh[2], bl[2];
            LDSM4(ah, aAhi + 128 * cc + 32 * ks);
            LDSM4(al, aAlo + 128 * cc + 32 * ks);
            LDSM2(bh, wb + 32 * ks);
            LDSM2(bl, wb + 1152 + 32 * ks);
            mma16816(C0, ah, bh);
            mma16816(C1, ah, bl);
            mma16816(C2, al, bh);
        }
        if (c == 0) { issueW(2, 0); issueHE(1, 1); CPCOMMIT(); }  // G2
        if (c == 1) { issueW(3, 1); CPCOMMIT(); }                 // G3
    }

    // -- Ep (f32 partials): kh pane, rows l>>2 & +8, cols 8ro+2(l&3)+{0,1} --
    {
        const int r1 = l >> 2, cb = 8 * ro + 2 * (l & 3);
        char* ep = sm + OFF_EP + kh * 4352;
        *(float2*)(ep + r1 * 272 + cb * 4) =
            make_float2(C0[0] + C1[0] + C2[0], C0[1] + C1[1] + C2[1]);
        *(float2*)(ep + (r1 + 8) * 272 + cb * 4) =
            make_float2(C0[2] + C1[2] + C2[2], C0[3] + C1[3] + C2[3]);
    }
    __syncthreads();                                  // barrier #2

    // -- reduce kh halves -> E panes (2 cols/thread) --
    {
        int s = t >> 5, c = t & 31;                   // col pair 2c, 2c+1
        float2 a = *(const float2*)(sm + OFF_EP + s * 272 + c * 8);
        float2 b2 = *(const float2*)(sm + OFF_EP + 4352 + s * 272 + c * 8);
        float e0 = a.x + b2.x, e1 = a.y + b2.y;
        float q0, q1;
        float h0 = bt(e0, q0), h1 = bt(e1, q1);
        *(uint32_t*)(sm + OFF_EHI + s * 144 + c * 4) = pk(h0, h1);
        *(uint32_t*)(sm + OFF_ELO + s * 144 + c * 4) = pk(q0, q1);
    }
    __syncthreads();                                  // barrier #3: E ready

    // -- phase 2: A frags once, then 4 streamed he sub-slices --
    uint32_t eh[4][4], el[4][4];
    #pragma unroll
    for (int ks = 0; ks < 4; ++ks) {
        LDSM4(eh[ks], smb + OFF_EHI + arow * 144 + akb + 32 * ks);
        LDSM4(el[ks], smb + OFF_ELO + arow * 144 + akb + 32 * ks);
    }
    #pragma unroll 1
    for (int ss = 0; ss < 4; ++ss) {
        if (ss == 2) { CPWAIT(1); __syncwarp(); }     // he2 (G4) ready
        if (ss == 3) { CPWAIT(0); __syncwarp(); }     // he3 (G5) ready
        const uint32_t hb = heB + (ss & 1) * 2304 + bWl;
        float C[4] = {0, 0, 0, 0};
        #pragma unroll
        for (int ks = 0; ks < 4; ++ks) {
            uint32_t bh[2], bl[2];
            LDSM2(bh, hb + 32 * ks);
            LDSM2(bl, hb + 1152 + 32 * ks);
            mma16816(C, eh[ks], bh);
            mma16816(C, eh[ks], bl);
            mma16816(C, el[ks], bh);
        }
        // store rows (l>>2, +8), cols 32w + 8ss + 2(l&3) + {0,1}
        const int r1 = l >> 2;
        float* o1 = out + (size_t)(bb * SDIM + s0 + r1) * HDIM
                    + 32 * w + 8 * ss + 2 * (l & 3);
        o1[0] = C[0]; o1[1] = C[1];
        float* o2 = o1 + 8 * HDIM;
        o2[0] = C[2]; o2[1] = C[3];
        if (ss == 0) { issueHE(2, 0); CPCOMMIT(); }   // G4
        if (ss == 1) { issueHE(3, 1); CPCOMMIT(); }   // G5
    }
}

extern "C" void kernel_launch(void* const* d_in, const int* in_sizes, int n_in,
                              void* d_out, int out_size) {
    // metadata order: hidden_states, all_indices (unused: enumerates (s,h)
    // row-major per setup_inputs), W_seq, hidden_embeddings, cp_weight
    const float* hs = (const float*)d_in[0];
    const float* Wq = (const float*)d_in[2];
    const float* he = (const float*)d_in[3];
    const float* cp = (const float*)d_in[4];
    float* out = (float*)d_out;

    prep_kernel<<<32, 256>>>(Wq, he, cp);
    cudaFuncSetAttribute(cpc_mma, cudaFuncAttributeMaxDynamicSharedMemorySize,
                         SMEM_BYTES);
    cpc_mma<<<128, 512, SMEM_BYTES>>>(hs, out);
}